// round 2
// baseline (speedup 1.0000x reference)
#include <cuda_runtime.h>

// SoftmaxRefMatcher: fused cosine-sim GEMM + temperature softmax + coord expectation.
// Shapes: BW=8, C=64, N=256, WIDTH=256 (HW=65536), WINDOW=4 -> B=2, NW=6 target frames.
// Output layout (float32, 4620 elems): pseudo_coords (6*256*2) | scores[tgt_ids] (6*256)
//                                      | tgt_ids (6) | src_ids (6)

#define CK    64
#define NKP   256
#define HW    65536
#define NW    6
#define BM    128          // pixels per block tile
#define NCHUNK 512         // HW / BM

__device__ float g_tgt[NW * CK * NKP];          // normalized target descriptors [w][c][n]
__device__ float g_srcinv[2 * HW];              // per-pixel inverse L2 norm of src frames
__device__ float g_part[(size_t)NW * NKP * NCHUNK * 3];  // partials [w][kp][chunk][{sum,su,sv}]

// ---------------------------------------------------------------- tgt normalize
__global__ void k_norm_tgt(const float* __restrict__ kd) {
    int w = blockIdx.x, n = threadIdx.x;
    int f = (w / 3) * 4 + (w % 3) + 1;          // tgt frame ids: 1,2,3,5,6,7
    const float* src = kd + f * CK * NKP + n;
    float ss = 0.f;
    #pragma unroll
    for (int c = 0; c < CK; c++) { float x = src[c * NKP]; ss += x * x; }
    float inv = 1.f / fmaxf(sqrtf(ss), 1e-12f);
    float* dst = g_tgt + w * CK * NKP + n;
    #pragma unroll
    for (int c = 0; c < CK; c++) dst[c * NKP] = src[c * NKP] * inv;
}

// ---------------------------------------------------------------- src inv-norms
__global__ void k_src_inv(const float* __restrict__ dd) {
    int t = blockIdx.x * blockDim.x + threadIdx.x;   // 0 .. 2*HW-1
    int b = t >> 16, m = t & (HW - 1);
    const float* src = dd + (size_t)(b * 4) * CK * HW + m;
    float ss = 0.f;
    #pragma unroll
    for (int c = 0; c < CK; c++) { float x = src[(size_t)c * HW]; ss += x * x; }
    g_srcinv[t] = 1.f / fmaxf(sqrtf(ss), 1e-12f);
}

// ---------------------------------------------------------------- main fused GEMM+softmax partials
__global__ __launch_bounds__(512, 1) void k_main(const float* __restrict__ dd) {
    extern __shared__ float smem[];
    float* sA   = smem;                 // [64][256] normalized tgt (64 KB)
    float* sB   = smem + CK * NKP;      // [64][128] raw src tile  (32 KB)
    float* sInv = sB + CK * BM;         // [128]

    int w = blockIdx.y, chunk = blockIdx.x;
    int b = w / 3, srcf = b * 4;
    int m0 = chunk * BM;
    int tid = threadIdx.x;

    // load A: whole normalized tgt frame, contiguous
    {
        const float4* gA = (const float4*)(g_tgt + (size_t)w * CK * NKP);
        float4* s4 = (float4*)sA;
        #pragma unroll
        for (int i = 0; i < 8; i++) s4[tid + i * 512] = gA[tid + i * 512];   // 4096 float4
    }
    // load B: 64 rows x 128 px from desc_dense[srcf]
    {
        const float* gB = dd + (size_t)srcf * CK * HW;
        float4* s4 = (float4*)sB;
        #pragma unroll
        for (int i = 0; i < 4; i++) {
            int idx = tid + i * 512;            // 0..2047
            int k = idx >> 5, q = idx & 31;
            s4[k * 32 + q] = *(const float4*)(gB + (size_t)k * HW + m0 + q * 4);
        }
    }
    if (tid < BM) sInv[tid] = g_srcinv[b * HW + m0 + tid];
    __syncthreads();

    int tx = tid & 15;        // pixel group: 8 px each
    int ty = tid >> 4;        // kp group (0..31): 8 kp each

    unsigned long long acc[8][4];
    #pragma unroll
    for (int i = 0; i < 8; i++)
        #pragma unroll
        for (int j = 0; j < 4; j++) acc[i][j] = 0ull;

    const float* aBase = sA + ty * 8;
    const float* bBase = sB + tx * 8;

    #pragma unroll 16
    for (int k = 0; k < CK; k++) {
        float4 a0 = *(const float4*)(aBase + k * NKP);
        float4 a1 = *(const float4*)(aBase + k * NKP + 4);
        ulonglong2 bl0 = *(const ulonglong2*)(bBase + k * BM);
        ulonglong2 bl1 = *(const ulonglong2*)(bBase + k * BM + 4);
        unsigned long long bv[4] = { bl0.x, bl0.y, bl1.x, bl1.y };
        float av[8] = { a0.x, a0.y, a0.z, a0.w, a1.x, a1.y, a1.z, a1.w };
        #pragma unroll
        for (int i = 0; i < 8; i++) {
            unsigned long long ap;
            unsigned ai = __float_as_uint(av[i]);
            asm("mov.b64 %0, {%1, %1};" : "=l"(ap) : "r"(ai));
            #pragma unroll
            for (int j = 0; j < 4; j++)
                asm("fma.rn.f32x2 %0, %1, %2, %0;" : "+l"(acc[i][j]) : "l"(ap), "l"(bv[j]));
        }
    }

    // epilogue: exp(logit - 100) and per-thread partials (reads only sInv)
    float part[8][3];
    #pragma unroll
    for (int i = 0; i < 8; i++) {
        float ssum = 0.f, su = 0.f, sv = 0.f;
        #pragma unroll
        for (int j = 0; j < 4; j++) {
            unsigned long long a = acc[i][j];
            float d0 = __uint_as_float((unsigned)a);
            float d1 = __uint_as_float((unsigned)(a >> 32));
            int p0 = tx * 8 + 2 * j;
            int p1 = p0 + 1;
            float e0 = __expf(fmaf(d0 * sInv[p0], 100.f, -100.f));
            float e1 = __expf(fmaf(d1 * sInv[p1], 100.f, -100.f));
            int mg0 = m0 + p0, mg1 = m0 + p1;
            float u0 = (float)(mg0 & 255), v0 = (float)(mg0 >> 8);
            float u1 = (float)(mg1 & 255), v1 = (float)(mg1 >> 8);
            ssum += e0 + e1;
            su = fmaf(e0, u0, su); su = fmaf(e1, u1, su);
            sv = fmaf(e0, v0, sv); sv = fmaf(e1, v1, sv);
        }
        part[i][0] = ssum; part[i][1] = su; part[i][2] = sv;
    }

    __syncthreads();                         // everyone done reading sA/sB
    float* sP = sA;                          // reuse: [kp][tx][3], stride 48
    #pragma unroll
    for (int i = 0; i < 8; i++) {
        int kp = ty * 8 + i;
        float* d = sP + kp * 48 + tx * 3;
        d[0] = part[i][0]; d[1] = part[i][1]; d[2] = part[i][2];
    }
    __syncthreads();

    for (int o = tid; o < NKP * 3; o += 512) {
        int kp = o / 3, c = o - kp * 3;
        float s = 0.f;
        #pragma unroll
        for (int t = 0; t < 16; t++) s += sP[kp * 48 + t * 3 + c];
        g_part[(((size_t)w * NKP + kp) * NCHUNK + chunk) * 3 + c] = s;
    }
}

// ---------------------------------------------------------------- deterministic partial reduce
__global__ void k_reduce(float* __restrict__ out) {
    __shared__ float r0[256], r1[256], r2[256];
    int w = blockIdx.x >> 8, kp = blockIdx.x & 255;
    const float* p = g_part + ((size_t)w * NKP + kp) * NCHUNK * 3;
    int t = threadIdx.x;
    float s0 = p[t * 3]     + p[(t + 256) * 3];
    float s1 = p[t * 3 + 1] + p[(t + 256) * 3 + 1];
    float s2 = p[t * 3 + 2] + p[(t + 256) * 3 + 2];
    r0[t] = s0; r1[t] = s1; r2[t] = s2;
    __syncthreads();
    for (int s = 128; s > 0; s >>= 1) {
        if (t < s) { r0[t] += r0[t + s]; r1[t] += r1[t + s]; r2[t] += r2[t + s]; }
        __syncthreads();
    }
    if (t == 0) {
        float inv = 1.f / r0[0];
        int o = (w * NKP + kp) * 2;
        out[o]     = r1[0] * inv;
        out[o + 1] = r2[0] * inv;
    }
}

// ---------------------------------------------------------------- scores gather + ids
__global__ void k_tail(const float* __restrict__ scores, float* __restrict__ out) {
    int w = blockIdx.x, n = threadIdx.x;
    int f = (w / 3) * 4 + (w % 3) + 1;
    out[3072 + w * NKP + n] = scores[f * NKP + n];
    if (n == 0) {
        out[4608 + w] = (float)f;                 // tgt_ids: 1,2,3,5,6,7
        out[4614 + w] = (float)((w / 3) * 4);     // src_ids: 0,0,0,4,4,4
    }
}

extern "C" void kernel_launch(void* const* d_in, const int* in_sizes, int n_in,
                              void* d_out, int out_size) {
    (void)in_sizes; (void)n_in; (void)out_size;
    const float* scores = (const float*)d_in[0];
    const float* kd     = (const float*)d_in[1];
    const float* dd     = (const float*)d_in[2];
    // d_in[3] (keypoint_coords) is unused by the reference output.
    float* out = (float*)d_out;

    cudaFuncSetAttribute(k_main, cudaFuncAttributeMaxDynamicSharedMemorySize, 100 * 1024);

    k_norm_tgt<<<NW, 256>>>(kd);
    k_src_inv<<<512, 256>>>(dd);
    size_t smem = (CK * NKP + CK * BM + BM) * sizeof(float);
    k_main<<<dim3(NCHUNK, NW), 512, smem>>>(dd);
    k_reduce<<<NW * NKP, 256>>>(out);
    k_tail<<<NW, 256>>>(scores, out);
}

// round 4
// speedup vs baseline: 2.0775x; 2.0775x over previous
#include <cuda_runtime.h>
#include <cuda_bf16.h>
#include <cstdint>

// SoftmaxRefMatcher via mma.sync bf16 hi/lo split (base PTX ISA; harness targets
// compute_103 so no tcgen05/'a' features are available).
// exp(100*cos-100) fixed-shift softmax, per-tile partials, deterministic reduce.
// BW=8, C=64, N=256, HW=65536, WINDOW=4 -> B=2, NW=6.

#define CK     64
#define NKP    256
#define HW     65536
#define NW     6
#define TPX    128        // pixels per CTA
#define NTILE  512        // HW / TPX

__device__ __align__(256) __nv_bfloat16 g_Ahi[NW * NKP * CK];
__device__ __align__(256) __nv_bfloat16 g_Alo[NW * NKP * CK];
__device__ __align__(256) __nv_bfloat16 g_Bhi[2 * HW * CK];
__device__ __align__(256) __nv_bfloat16 g_Blo[2 * HW * CK];
__device__ __align__(256) float g_part[NW * NKP * NTILE * 2];  // [row][tile][{sum,su}]

__device__ __forceinline__ uint32_t smem_u32(const void* p) {
    uint32_t a;
    asm("{ .reg .u64 t; cvta.to.shared.u64 t, %1; cvt.u32.u64 %0, t; }" : "=r"(a) : "l"(p));
    return a;
}
#define LDSM4(R, addr) \
    asm volatile("ldmatrix.sync.aligned.m8n8.x4.shared.b16 {%0,%1,%2,%3}, [%4];" \
        : "=r"((R)[0]), "=r"((R)[1]), "=r"((R)[2]), "=r"((R)[3]) : "r"(addr))
#define MMA16816(D, A, b0, b1) \
    asm volatile("mma.sync.aligned.m16n8k16.row.col.f32.bf16.bf16.f32 " \
        "{%0,%1,%2,%3}, {%4,%5,%6,%7}, {%8,%9}, {%0,%1,%2,%3};" \
        : "+f"((D)[0]), "+f"((D)[1]), "+f"((D)[2]), "+f"((D)[3]) \
        : "r"((A)[0]), "r"((A)[1]), "r"((A)[2]), "r"((A)[3]), "r"(b0), "r"(b1))

__device__ __forceinline__ void split_bf16(float x, __nv_bfloat16& hi, __nv_bfloat16& lo) {
    hi = __float2bfloat16(x);
    lo = __float2bfloat16(x - __bfloat162float(hi));
}

// ---------------------------------------------------------------- tgt prep
__global__ void k_prep_tgt(const float* __restrict__ kd) {
    int w = blockIdx.x, n = threadIdx.x;
    int f = (w / 3) * 4 + (w % 3) + 1;
    const float* src = kd + f * CK * NKP + n;
    float v[CK]; float ss = 0.f;
    #pragma unroll
    for (int c = 0; c < CK; c++) { v[c] = src[c * NKP]; ss += v[c] * v[c]; }
    float inv = 1.f / fmaxf(sqrtf(ss), 1e-12f);
    int base = (w * NKP + n) * CK;
    #pragma unroll
    for (int c = 0; c < CK; c++) {
        __nv_bfloat16 hi, lo; split_bf16(v[c] * inv, hi, lo);
        g_Ahi[base + c] = hi; g_Alo[base + c] = lo;
    }
}

// ---------------------------------------------------------------- src prep (transpose to [px][c])
__global__ __launch_bounds__(128) void k_prep_src(const float* __restrict__ dd) {
    __shared__ uint32_t sH[128 * 33], sL[128 * 33];
    int tid = threadIdx.x;
    int pidx = blockIdx.x * 128 + tid;
    int b = pidx >> 16;
    const float* src = dd + (size_t)(b * 4) * CK * HW + (pidx & (HW - 1));
    float v[CK]; float ss = 0.f;
    #pragma unroll
    for (int c = 0; c < CK; c++) { v[c] = src[(size_t)c * HW]; ss += v[c] * v[c]; }
    float inv = 1.f / fmaxf(sqrtf(ss), 1e-12f);
    #pragma unroll
    for (int j = 0; j < 32; j++) {
        __nv_bfloat16 h0, l0, h1, l1;
        split_bf16(v[2 * j] * inv, h0, l0);
        split_bf16(v[2 * j + 1] * inv, h1, l1);
        sH[tid * 33 + j] = (uint32_t)__bfloat16_as_ushort(h0) | ((uint32_t)__bfloat16_as_ushort(h1) << 16);
        sL[tid * 33 + j] = (uint32_t)__bfloat16_as_ushort(l0) | ((uint32_t)__bfloat16_as_ushort(l1) << 16);
    }
    __syncthreads();
    uint32_t* oH = reinterpret_cast<uint32_t*>(g_Bhi) + (size_t)blockIdx.x * 128 * 32;
    uint32_t* oL = reinterpret_cast<uint32_t*>(g_Blo) + (size_t)blockIdx.x * 128 * 32;
    #pragma unroll
    for (int i = 0; i < 32; i++) {
        int u = tid + i * 128;
        int mm = u >> 5, j = u & 31;
        oH[u] = sH[mm * 33 + j];
        oL[u] = sL[mm * 33 + j];
    }
}

// ---------------------------------------------------------------- main GEMM + softmax partials
// smem rows padded to 72 bf16 (144B) -> conflict-free ldmatrix.
#define PADB 144
#define SZA (256 * PADB)
#define SZB (128 * PADB)
#define SM_TOTAL (2 * SZA + 2 * SZB + 256 * 4 * 4)

__global__ __launch_bounds__(512, 1) void k_gemm() {
    extern __shared__ char smem[];
    char* sAH = smem;
    char* sAL = smem + SZA;
    char* sBH = smem + 2 * SZA;
    char* sBL = smem + 2 * SZA + SZB;
    float* sRed = (float*)(smem + 2 * SZA + 2 * SZB);   // [256][4]

    int tid = threadIdx.x;
    int w = blockIdx.y, tile = blockIdx.x;
    int b = w / 3;

    // A: 256 rows x 64 bf16 (hi & lo), 2048 uint4 each
    {
        const uint4* gAH = (const uint4*)(g_Ahi + (size_t)w * NKP * CK);
        const uint4* gAL = (const uint4*)(g_Alo + (size_t)w * NKP * CK);
        #pragma unroll
        for (int i = 0; i < 4; i++) {
            int idx = tid + i * 512;
            int r = idx >> 3, c = idx & 7;
            *(uint4*)(sAH + r * PADB + c * 16) = gAH[idx];
            *(uint4*)(sAL + r * PADB + c * 16) = gAL[idx];
        }
        const uint4* gBH = (const uint4*)(g_Bhi + (size_t)(b * HW + tile * TPX) * CK);
        const uint4* gBL = (const uint4*)(g_Blo + (size_t)(b * HW + tile * TPX) * CK);
        #pragma unroll
        for (int i = 0; i < 2; i++) {
            int idx = tid + i * 512;
            int r = idx >> 3, c = idx & 7;
            *(uint4*)(sBH + r * PADB + c * 16) = gBH[idx];
            *(uint4*)(sBL + r * PADB + c * 16) = gBL[idx];
        }
    }
    __syncthreads();

    int lane = tid & 31, wid = tid >> 5;
    int wm = wid & 7, wn = wid >> 3;        // warp tile: 32 (m) x 64 (n)
    int m0 = wm * 32, n0 = wn * 64;

    float acc[2][8][4];
    #pragma unroll
    for (int i = 0; i < 2; i++)
        #pragma unroll
        for (int j = 0; j < 8; j++)
            #pragma unroll
            for (int q = 0; q < 4; q++) acc[i][j][q] = 0.f;

    // ldmatrix per-lane source rows/cols
    int aRow = (lane & 7) + ((lane >> 3) & 1) * 8;       // + m16 base
    int aColB = (((lane >> 4) & 1) * 8) * 2;             // byte offset
    int bRow = (lane & 7) + ((lane >> 4) & 1) * 8;       // + n16 base
    int bColB = (((lane >> 3) & 1) * 8) * 2;

    const char* Ap[3] = { sAH, sAH, sAL };
    const char* Bp[3] = { sBH, sBL, sBH };

    #pragma unroll
    for (int p = 0; p < 3; p++) {
        uint32_t aBase = smem_u32(Ap[p]) + (uint32_t)(m0 + aRow) * PADB + aColB;
        uint32_t bBase = smem_u32(Bp[p]) + (uint32_t)(n0 + bRow) * PADB + bColB;
        #pragma unroll
        for (int ks = 0; ks < 4; ks++) {
            uint32_t koff = ks * 32;                     // 16 bf16 = 32B
            uint32_t A0[4], A1[4], Bf[4][4];
            LDSM4(A0, aBase + koff);
            LDSM4(A1, aBase + 16 * PADB + koff);
            #pragma unroll
            for (int q = 0; q < 4; q++) LDSM4(Bf[q], bBase + q * 16 * PADB + koff);
            #pragma unroll
            for (int nt = 0; nt < 8; nt++) {
                uint32_t b0 = Bf[nt >> 1][(nt & 1) * 2];
                uint32_t b1 = Bf[nt >> 1][(nt & 1) * 2 + 1];
                MMA16816(acc[0][nt], A0, b0, b1);
                MMA16816(acc[1][nt], A1, b0, b1);
            }
        }
    }

    // ---- fused softmax epilogue on register accumulators ----
    int g = lane >> 2, t = lane & 3;
    const float K1 = 144.2695041f;                       // 100 * log2(e)
    #pragma unroll
    for (int mt = 0; mt < 2; mt++) {
        float s0 = 0.f, u0 = 0.f, s1 = 0.f, u1 = 0.f;
        #pragma unroll
        for (int nt = 0; nt < 8; nt++) {
            float col = (float)(n0 + nt * 8 + t * 2);
            float e0, e1, e2, e3;
            asm("ex2.approx.ftz.f32 %0, %1;" : "=f"(e0) : "f"(fmaf(acc[mt][nt][0], K1, -K1)));
            asm("ex2.approx.ftz.f32 %0, %1;" : "=f"(e1) : "f"(fmaf(acc[mt][nt][1], K1, -K1)));
            asm("ex2.approx.ftz.f32 %0, %1;" : "=f"(e2) : "f"(fmaf(acc[mt][nt][2], K1, -K1)));
            asm("ex2.approx.ftz.f32 %0, %1;" : "=f"(e3) : "f"(fmaf(acc[mt][nt][3], K1, -K1)));
            s0 += e0 + e1;  u0 = fmaf(e0, col, u0); u0 = fmaf(e1, col + 1.f, u0);
            s1 += e2 + e3;  u1 = fmaf(e2, col, u1); u1 = fmaf(e3, col + 1.f, u1);
        }
        // reduce over the 4 lanes sharing a row (t = 0..3) — fixed pairwise order
        #pragma unroll
        for (int d = 1; d <= 2; d <<= 1) {
            s0 += __shfl_xor_sync(0xFFFFFFFF, s0, d);
            u0 += __shfl_xor_sync(0xFFFFFFFF, u0, d);
            s1 += __shfl_xor_sync(0xFFFFFFFF, s1, d);
            u1 += __shfl_xor_sync(0xFFFFFFFF, u1, d);
        }
        if (t == 0) {
            int r0 = m0 + mt * 16 + g;
            sRed[r0 * 4 + wn * 2 + 0] = s0;
            sRed[r0 * 4 + wn * 2 + 1] = u0;
            sRed[(r0 + 8) * 4 + wn * 2 + 0] = s1;
            sRed[(r0 + 8) * 4 + wn * 2 + 1] = u1;
        }
    }
    __syncthreads();
    if (tid < 256) {
        float s = sRed[tid * 4 + 0] + sRed[tid * 4 + 2];
        float u = sRed[tid * 4 + 1] + sRed[tid * 4 + 3];
        size_t row = (size_t)w * NKP + tid;
        g_part[(row * NTILE + tile) * 2 + 0] = s;
        g_part[(row * NTILE + tile) * 2 + 1] = u;
    }
}

// ---------------------------------------------------------------- deterministic reduce -> coords
__global__ void k_reduce(float* __restrict__ out) {
    __shared__ float r0[256], r1[256], r2[256];
    int row = blockIdx.x, t = threadIdx.x;
    const float* p = g_part + (size_t)row * NTILE * 2;
    float s = 0.f, u = 0.f, v = 0.f;
    #pragma unroll
    for (int i = 0; i < 2; i++) {
        int tl = t + i * 256;
        float ps = p[2 * tl], pu = p[2 * tl + 1];
        s += ps;
        u += fmaf((float)((tl & 1) * 128), ps, pu);   // global u = (tile&1)*128 + local
        v = fmaf((float)(tl >> 1), ps, v);            // v = tile >> 1 (constant per tile)
    }
    r0[t] = s; r1[t] = u; r2[t] = v;
    __syncthreads();
    for (int st = 128; st > 0; st >>= 1) {
        if (t < st) { r0[t] += r0[t + st]; r1[t] += r1[t + st]; r2[t] += r2[t + st]; }
        __syncthreads();
    }
    if (t == 0) {
        float inv = 1.f / r0[0];
        out[row * 2 + 0] = r1[0] * inv;
        out[row * 2 + 1] = r2[0] * inv;
    }
}

// ---------------------------------------------------------------- scores + ids tail
__global__ void k_tail(const float* __restrict__ scores, float* __restrict__ out) {
    int w = blockIdx.x, n = threadIdx.x;
    int f = (w / 3) * 4 + (w % 3) + 1;
    out[3072 + w * NKP + n] = scores[f * NKP + n];
    if (n == 0) {
        out[4608 + w] = (float)f;
        out[4614 + w] = (float)((w / 3) * 4);
    }
}

extern "C" void kernel_launch(void* const* d_in, const int* in_sizes, int n_in,
                              void* d_out, int out_size) {
    (void)in_sizes; (void)n_in; (void)out_size;
    const float* scores = (const float*)d_in[0];
    const float* kd     = (const float*)d_in[1];
    const float* dd     = (const float*)d_in[2];
    float* out = (float*)d_out;

    cudaFuncSetAttribute(k_gemm, cudaFuncAttributeMaxDynamicSharedMemorySize, SM_TOTAL);

    k_prep_tgt<<<NW, 256>>>(kd);
    k_prep_src<<<2 * HW / 128, 128>>>(dd);
    k_gemm<<<dim3(NTILE, NW), 512, SM_TOTAL>>>();
    k_reduce<<<NW * NKP, 256>>>(out);
    k_tail<<<NW, 256>>>(scores, out);
}

// round 5
// speedup vs baseline: 3.0266x; 1.4568x over previous
#include <cuda_runtime.h>
#include <cuda_bf16.h>
#include <cstdint>

// SoftmaxRefMatcher: persistent mma.sync bf16 hi/lo GEMM + fused fixed-shift softmax.
// BW=8, C=64, N=256, HW=65536, WINDOW=4 -> B=2, NW=6 (w frames), 12 (w,kh) groups.

#define CK     64
#define NKP    256
#define HW     65536
#define NW     6
#define TPX    128
#define NTILE  512
#define NGRP   12
#define CPG    49
#define NCTA   (NGRP * CPG)     // 588

__device__ __align__(256) __nv_bfloat16 g_Ahi[NW * NKP * CK];
__device__ __align__(256) __nv_bfloat16 g_Alo[NW * NKP * CK];
__device__ __align__(256) __nv_bfloat16 g_Bhi[2 * HW * CK];
__device__ __align__(256) __nv_bfloat16 g_Blo[2 * HW * CK];
__device__ __align__(256) float g_part[NW * NKP * NTILE * 2];   // [row][tile][{sum,su}]

__device__ __forceinline__ uint32_t smem_u32(const void* p) {
    uint32_t a;
    asm("{ .reg .u64 t; cvta.to.shared.u64 t, %1; cvt.u32.u64 %0, t; }" : "=r"(a) : "l"(p));
    return a;
}
#define LDSM4(R, addr) \
    asm volatile("ldmatrix.sync.aligned.m8n8.x4.shared.b16 {%0,%1,%2,%3}, [%4];" \
        : "=r"((R)[0]), "=r"((R)[1]), "=r"((R)[2]), "=r"((R)[3]) : "r"(addr))
#define MMA16816(D, A, b0, b1) \
    asm volatile("mma.sync.aligned.m16n8k16.row.col.f32.bf16.bf16.f32 " \
        "{%0,%1,%2,%3}, {%4,%5,%6,%7}, {%8,%9}, {%0,%1,%2,%3};" \
        : "+f"((D)[0]), "+f"((D)[1]), "+f"((D)[2]), "+f"((D)[3]) \
        : "r"((A)[0]), "r"((A)[1]), "r"((A)[2]), "r"((A)[3]), "r"(b0), "r"(b1))
#define CP16(dst, src) \
    asm volatile("cp.async.cg.shared.global [%0], [%1], 16;" :: "r"(dst), "l"(src))
#define CP_COMMIT() asm volatile("cp.async.commit_group;" ::: "memory")
#define CP_WAIT1()  asm volatile("cp.async.wait_group 1;" ::: "memory")

__device__ __forceinline__ void split_bf16(float x, __nv_bfloat16& hi, __nv_bfloat16& lo) {
    hi = __float2bfloat16(x);
    lo = __float2bfloat16(x - __bfloat162float(hi));
}

// ---------------------------------------------------------------- merged prep
__global__ __launch_bounds__(128) void k_prep(const float* __restrict__ kd,
                                              const float* __restrict__ dd) {
    int bid = blockIdx.x, tid = threadIdx.x;
    if (bid < 1024) {
        // ---- src: normalize + bf16 split + transpose to [pixel][channel] ----
        __shared__ uint32_t sH[128 * 33], sL[128 * 33];
        int pidx = bid * 128 + tid;
        int b = pidx >> 16;
        const float* src = dd + (size_t)(b * 4) * CK * HW + (pidx & (HW - 1));
        float v[CK]; float ss = 0.f;
        #pragma unroll
        for (int c = 0; c < CK; c++) { v[c] = src[(size_t)c * HW]; ss += v[c] * v[c]; }
        float inv = 1.f / fmaxf(sqrtf(ss), 1e-12f);
        #pragma unroll
        for (int j = 0; j < 32; j++) {
            __nv_bfloat16 h0, l0, h1, l1;
            split_bf16(v[2 * j] * inv, h0, l0);
            split_bf16(v[2 * j + 1] * inv, h1, l1);
            sH[tid * 33 + j] = (uint32_t)__bfloat16_as_ushort(h0) | ((uint32_t)__bfloat16_as_ushort(h1) << 16);
            sL[tid * 33 + j] = (uint32_t)__bfloat16_as_ushort(l0) | ((uint32_t)__bfloat16_as_ushort(l1) << 16);
        }
        __syncthreads();
        uint32_t* oH = reinterpret_cast<uint32_t*>(g_Bhi) + (size_t)bid * 128 * 32;
        uint32_t* oL = reinterpret_cast<uint32_t*>(g_Blo) + (size_t)bid * 128 * 32;
        #pragma unroll
        for (int i = 0; i < 32; i++) {
            int u = tid + i * 128;
            int mm = u >> 5, j = u & 31;
            oH[u] = sH[mm * 33 + j];
            oL[u] = sL[mm * 33 + j];
        }
    } else {
        // ---- tgt: normalize + split, layout [w][n][c] ----
        int idx = bid - 1024;               // 0..11
        int w = idx >> 1;
        int n = (idx & 1) * 128 + tid;
        int f = (w / 3) * 4 + (w % 3) + 1;
        const float* src = kd + f * CK * NKP + n;
        float v[CK]; float ss = 0.f;
        #pragma unroll
        for (int c = 0; c < CK; c++) { v[c] = src[c * NKP]; ss += v[c] * v[c]; }
        float inv = 1.f / fmaxf(sqrtf(ss), 1e-12f);
        int base = (w * NKP + n) * CK;
        #pragma unroll
        for (int c = 0; c < CK; c++) {
            __nv_bfloat16 hi, lo; split_bf16(v[c] * inv, hi, lo);
            g_Ahi[base + c] = hi; g_Alo[base + c] = lo;
        }
    }
}

// ---------------------------------------------------------------- persistent GEMM + softmax
// smem: AH 16K | AL 16K | B buf0 (BH 16K, BL 16K) | buf1 (32K) | sRed 2K  = 100352 B
#define SM_A_H 0
#define SM_A_L 16384
#define SM_B(buf) (32768 + (buf) * 32768)
#define SM_RED 98304
#define SM_TOT (98304 + 2048)
// swizzled addr within a 128B-row region: row r, 16B-chunk c -> r*128 + ((c ^ (r&7))*16)

__global__ void __launch_bounds__(256, 2) k_gemm() {
    extern __shared__ char smem[];
    uint32_t sb = smem_u32(smem);
    float* sRed = (float*)(smem + SM_RED);
    int tid = threadIdx.x;
    int cta = blockIdx.x;
    int grp = cta % NGRP, j = cta / NGRP;
    int w = grp >> 1, kh = grp & 1, b = w / 3;
    int t0 = (j * NTILE) / CPG, t1 = ((j + 1) * NTILE) / CPG;

    // ---- prefetch A (once) + B(t0) into group 0 ----
    {
        const __nv_bfloat16* gAH = g_Ahi + (size_t)(w * NKP + kh * 128) * CK;
        const __nv_bfloat16* gAL = g_Alo + (size_t)(w * NKP + kh * 128) * CK;
        #pragma unroll
        for (int i = 0; i < 8; i++) {
            int ch = tid + i * 256;
            int reg = ch >> 10, c2 = ch & 1023;
            int row = c2 >> 3, c = c2 & 7;
            const __nv_bfloat16* src = (reg ? gAL : gAH) + row * CK + c * 8;
            uint32_t dst = sb + (reg ? SM_A_L : SM_A_H) + row * 128 + (((c ^ (row & 7))) << 4);
            CP16(dst, (const void*)src);
        }
    }
    const __nv_bfloat16* gBH = g_Bhi + (size_t)b * HW * CK;
    const __nv_bfloat16* gBL = g_Blo + (size_t)b * HW * CK;
    auto prefB = [&](int buf, int t) {
        #pragma unroll
        for (int i = 0; i < 8; i++) {
            int ch = tid + i * 256;
            int reg = ch >> 10, c2 = ch & 1023;
            int row = c2 >> 3, c = c2 & 7;
            const __nv_bfloat16* src = (reg ? gBL : gBH) + (size_t)(t * TPX + row) * CK + c * 8;
            uint32_t dst = sb + SM_B(buf) + reg * 16384 + row * 128 + (((c ^ (row & 7))) << 4);
            CP16(dst, (const void*)src);
        }
    };
    prefB(0, t0);
    CP_COMMIT();

    // ---- per-warp fragment addressing (verified round-4 maps + XOR swizzle) ----
    int lane = tid & 31, wid = tid >> 5;
    int m0 = (wid & 3) * 32, n0 = (wid >> 2) * 64, wn = wid >> 2;
    int aRow = (lane & 7) + ((lane >> 3) & 1) * 8;
    int aCh  = (lane >> 4) & 1;
    int bRow = (lane & 7) + ((lane >> 4) & 1) * 8;
    int bCh  = (lane >> 3) & 1;
    int rA0 = m0 + aRow, rA1 = rA0 + 16;
    uint32_t aH0 = sb + SM_A_H + rA0 * 128, aH1 = sb + SM_A_H + rA1 * 128;
    uint32_t aL0 = sb + SM_A_L + rA0 * 128, aL1 = sb + SM_A_L + rA1 * 128;
    int xA0 = rA0 & 7, xA1 = rA1 & 7;
    uint32_t bOff[4]; int xB[4];
    #pragma unroll
    for (int q = 0; q < 4; q++) {
        int rB = n0 + q * 16 + bRow;
        bOff[q] = rB * 128; xB[q] = rB & 7;
    }
    int g = lane >> 2, t4 = lane & 3;
    const float K1 = 144.2695041f;          // 100 * log2(e)

    int buf = 0;
    for (int t = t0; t < t1; t++) {
        if (t + 1 < t1) prefB(buf ^ 1, t + 1);
        CP_COMMIT();
        CP_WAIT1();
        __syncthreads();

        float acc[2][8][4];
        #pragma unroll
        for (int i = 0; i < 2; i++)
            #pragma unroll
            for (int nt = 0; nt < 8; nt++)
                #pragma unroll
                for (int q = 0; q < 4; q++) acc[i][nt][q] = 0.f;

        uint32_t bB = sb + SM_B(buf);
        #pragma unroll
        for (int ks = 0; ks < 4; ks++) {
            uint32_t A0h[4], A1h[4], A0l[4], A1l[4], Bf[4][4];
            int chA = aCh + 2 * ks;
            LDSM4(A0h, aH0 + ((chA ^ xA0) << 4));
            LDSM4(A1h, aH1 + ((chA ^ xA1) << 4));
            LDSM4(A0l, aL0 + ((chA ^ xA0) << 4));
            LDSM4(A1l, aL1 + ((chA ^ xA1) << 4));
            int chB = bCh + 2 * ks;
            #pragma unroll
            for (int q = 0; q < 4; q++) LDSM4(Bf[q], bB + bOff[q] + ((chB ^ xB[q]) << 4));
            #pragma unroll
            for (int nt = 0; nt < 8; nt++) {
                uint32_t b0 = Bf[nt >> 1][(nt & 1) * 2];
                uint32_t b1 = Bf[nt >> 1][(nt & 1) * 2 + 1];
                MMA16816(acc[0][nt], A0h, b0, b1);      // hi*hi
                MMA16816(acc[1][nt], A1h, b0, b1);
                MMA16816(acc[0][nt], A0l, b0, b1);      // lo*hi
                MMA16816(acc[1][nt], A1l, b0, b1);
            }
            #pragma unroll
            for (int q = 0; q < 4; q++) LDSM4(Bf[q], bB + 16384 + bOff[q] + ((chB ^ xB[q]) << 4));
            #pragma unroll
            for (int nt = 0; nt < 8; nt++) {
                uint32_t b0 = Bf[nt >> 1][(nt & 1) * 2];
                uint32_t b1 = Bf[nt >> 1][(nt & 1) * 2 + 1];
                MMA16816(acc[0][nt], A0h, b0, b1);      // hi*lo
                MMA16816(acc[1][nt], A1h, b0, b1);
            }
        }

        // ---- fused softmax epilogue ----
        #pragma unroll
        for (int mt = 0; mt < 2; mt++) {
            float s0 = 0.f, u0 = 0.f, s1 = 0.f, u1 = 0.f;
            #pragma unroll
            for (int nt = 0; nt < 8; nt++) {
                float col = (float)(n0 + nt * 8 + t4 * 2);
                float e0, e1, e2, e3;
                asm("ex2.approx.ftz.f32 %0, %1;" : "=f"(e0) : "f"(fmaf(acc[mt][nt][0], K1, -K1)));
                asm("ex2.approx.ftz.f32 %0, %1;" : "=f"(e1) : "f"(fmaf(acc[mt][nt][1], K1, -K1)));
                asm("ex2.approx.ftz.f32 %0, %1;" : "=f"(e2) : "f"(fmaf(acc[mt][nt][2], K1, -K1)));
                asm("ex2.approx.ftz.f32 %0, %1;" : "=f"(e3) : "f"(fmaf(acc[mt][nt][3], K1, -K1)));
                s0 += e0 + e1;  u0 = fmaf(e0, col, u0); u0 = fmaf(e1, col + 1.f, u0);
                s1 += e2 + e3;  u1 = fmaf(e2, col, u1); u1 = fmaf(e3, col + 1.f, u1);
            }
            #pragma unroll
            for (int d = 1; d <= 2; d <<= 1) {
                s0 += __shfl_xor_sync(0xFFFFFFFF, s0, d);
                u0 += __shfl_xor_sync(0xFFFFFFFF, u0, d);
                s1 += __shfl_xor_sync(0xFFFFFFFF, s1, d);
                u1 += __shfl_xor_sync(0xFFFFFFFF, u1, d);
            }
            if (t4 == 0) {
                int r = m0 + mt * 16 + g;
                sRed[r * 4 + wn * 2 + 0] = s0;
                sRed[r * 4 + wn * 2 + 1] = u0;
                sRed[(r + 8) * 4 + wn * 2 + 0] = s1;
                sRed[(r + 8) * 4 + wn * 2 + 1] = u1;
            }
        }
        __syncthreads();
        if (tid < 128) {
            float s = sRed[tid * 4 + 0] + sRed[tid * 4 + 2];
            float u = sRed[tid * 4 + 1] + sRed[tid * 4 + 3];
            size_t row = (size_t)w * NKP + kh * 128 + tid;
            g_part[(row * NTILE + t) * 2 + 0] = s;
            g_part[(row * NTILE + t) * 2 + 1] = u;
        }
        __syncthreads();            // protect sRed + B buffer reuse
        buf ^= 1;
    }
}

// ---------------------------------------------------------------- warp-per-row reduce
__global__ __launch_bounds__(256) void k_reduce(float* __restrict__ out) {
    int row = blockIdx.x * 8 + (threadIdx.x >> 5);     // 0..1535
    int lane = threadIdx.x & 31;
    const float4* p = (const float4*)(g_part + (size_t)row * NTILE * 2);
    float s = 0.f, u = 0.f, v = 0.f;
    #pragma unroll
    for (int i = 0; i < 8; i++) {
        int idx = lane + i * 32;                        // float4 = tiles {2idx, 2idx+1}
        float4 q = p[idx];
        float sp = q.x + q.z;
        s += sp;
        u += q.y + q.w + 128.f * q.z;
        v = fmaf((float)idx, sp, v);
    }
    #pragma unroll
    for (int d = 16; d > 0; d >>= 1) {
        s += __shfl_xor_sync(0xFFFFFFFF, s, d);
        u += __shfl_xor_sync(0xFFFFFFFF, u, d);
        v += __shfl_xor_sync(0xFFFFFFFF, v, d);
    }
    if (lane == 0) {
        float inv = 1.f / s;
        out[row * 2 + 0] = u * inv;
        out[row * 2 + 1] = v * inv;
    }
}

// ---------------------------------------------------------------- scores + ids tail
__global__ void k_tail(const float* __restrict__ scores, float* __restrict__ out) {
    int w = blockIdx.x, n = threadIdx.x;
    int f = (w / 3) * 4 + (w % 3) + 1;
    out[3072 + w * NKP + n] = scores[f * NKP + n];
    if (n == 0) {
        out[4608 + w] = (float)f;
        out[4614 + w] = (float)((w / 3) * 4);
    }
}

extern "C" void kernel_launch(void* const* d_in, const int* in_sizes, int n_in,
                              void* d_out, int out_size) {
    (void)in_sizes; (void)n_in; (void)out_size;
    const float* scores = (const float*)d_in[0];
    const float* kd     = (const float*)d_in[1];
    const float* dd     = (const float*)d_in[2];
    float* out = (float*)d_out;

    cudaFuncSetAttribute(k_gemm, cudaFuncAttributeMaxDynamicSharedMemorySize, SM_TOT);

    k_prep<<<1024 + NGRP, 128>>>(kd, dd);
    k_gemm<<<NCTA, 256, SM_TOT>>>();
    k_reduce<<<NW * NKP / 8, 256>>>(out);
    k_tail<<<NW, 256>>>(scores, out);
}